// round 15
// baseline (speedup 1.0000x reference)
#include <cuda_runtime.h>

#define BINS 64
#define BC 96                      // B*C = 32*3
#define PLANE4 65536               // 512*512/4 float4 per (b,c) plane
#define BPP 18                     // chunks per plane
#define THREADS 128
#define WARPS (THREADS / 32)       // 4
#define GRID (BC * BPP)            // 1728 <= 148*12 = 1776 -> SINGLE WAVE

// Signed per-(plane,bin) count diff (+input, -target). Zero at module load;
// the last block restores it to zero each call -> graph-replay safe.
__device__ int g_diff[BC * BINS];
__device__ unsigned int g_count;

// bin = clip(floor((v+1)/step), 0, 63). Input domain [-1,1) => result >= 0.
// Exact-edge disagreement with searchsorted is ~1e-6 relative loss noise.
__device__ __forceinline__ int bin_of(float v) {
    return min(__float2int_rd(fmaf(v, 31.5f, 31.5f)), 63);
}

// s8 packing, 4 bins/word: byte = lane*4 + (bin>>2)*128 + (bin&3)
// -> word = (bin>>2)*32 + lane, so word % 32 == lane for EVERY bin:
// strictly conflict-free LDS/STS, and each lane owns its bytes (no races).
__device__ __forceinline__ int off_of(int b) {
    return ((b & ~3) << 5) | (b & 3);          // (bin>>2)*128 + (bin&3)
}

__global__ __launch_bounds__(THREADS, 12)      // ~40 regs: room for 4-deep MLP
void fused_kernel(const float4* __restrict__ inp, const float4* __restrict__ tgt,
                  float* __restrict__ out) {
    __shared__ signed char hist[WARPS * 2048]; // 8 KB
    __shared__ unsigned int s_ticket;
    __shared__ float ssum[WARPS];

    const int tid  = threadIdx.x;
    const int lane = tid & 31;
    const int wid  = tid >> 5;

    int4* z4 = (int4*)hist;
    #pragma unroll
    for (int i = tid; i < (int)sizeof(hist) / 16; i += THREADS)
        z4[i] = make_int4(0, 0, 0, 0);
    __syncthreads();

    signed char* h = &hist[wid * 2048 + lane * 4];   // lane-owned byte column

    const int plane = blockIdx.x / BPP;
    const int chunk = blockIdx.x % BPP;
    // Exact uneven bounds (PLANE4 not divisible by 18).
    const int start4 = (chunk * PLANE4) / BPP;
    const int end4   = ((chunk + 1) * PLANE4) / BPP;
    const float4* __restrict__ a = inp + (size_t)plane * PLANE4;
    const float4* __restrict__ b = tgt + (size_t)plane * PLANE4;

    // <=114 values/tensor/thread -> per-bin diff in [-114, 114]: s8 ok.
    // 2-way unroll: 4 independent LDG.128 batched ahead of the RMW chain
    // (doubles per-warp MLP — the flat-58%-DRAM plateau across occupancies
    // showed per-warp load depth, not warp count, limits bandwidth).
    int i = start4 + tid;
    for (; i + THREADS < end4; i += 2 * THREADS) {
        float4 v0 = __ldcs(&a[i]);
        float4 v1 = __ldcs(&a[i + THREADS]);
        float4 u0 = __ldcs(&b[i]);
        float4 u1 = __ldcs(&b[i + THREADS]);
        h[off_of(bin_of(v0.x))] += 1;
        h[off_of(bin_of(v0.y))] += 1;
        h[off_of(bin_of(v0.z))] += 1;
        h[off_of(bin_of(v0.w))] += 1;
        h[off_of(bin_of(v1.x))] += 1;
        h[off_of(bin_of(v1.y))] += 1;
        h[off_of(bin_of(v1.z))] += 1;
        h[off_of(bin_of(v1.w))] += 1;
        h[off_of(bin_of(u0.x))] -= 1;
        h[off_of(bin_of(u0.y))] -= 1;
        h[off_of(bin_of(u0.z))] -= 1;
        h[off_of(bin_of(u0.w))] -= 1;
        h[off_of(bin_of(u1.x))] -= 1;
        h[off_of(bin_of(u1.y))] -= 1;
        h[off_of(bin_of(u1.z))] -= 1;
        h[off_of(bin_of(u1.w))] -= 1;
    }
    if (i < end4) {                            // tail: single iteration
        float4 v = __ldcs(&a[i]);
        float4 u = __ldcs(&b[i]);
        h[off_of(bin_of(v.x))] += 1;
        h[off_of(bin_of(v.y))] += 1;
        h[off_of(bin_of(v.z))] += 1;
        h[off_of(bin_of(v.w))] += 1;
        h[off_of(bin_of(u.x))] -= 1;
        h[off_of(bin_of(u.y))] -= 1;
        h[off_of(bin_of(u.z))] -= 1;
        h[off_of(bin_of(u.w))] -= 1;
    }
    __syncthreads();

    // Fold: thread t -> bin = t&63, half = t>>6 (warps 2h, 2h+1). Extract
    // byte (bin&3) from 2 warps x 32 lane-words via masked signed dp4a.
    // Lane rotation (l+t)&31 -> distinct banks within the folding warp.
    {
        const int bin  = tid & 63;
        const int half = tid >> 6;
        const int mask = 1 << ((bin & 3) * 8);
        int s = 0;
        #pragma unroll
        for (int w = 0; w < 2; w++) {
            const int* row = (const int*)hist + (2 * half + w) * 512 + (bin >> 2) * 32;
            #pragma unroll
            for (int l = 0; l < 32; l++)
                s = __dp4a(row[(l + tid) & 31], mask, s);
        }
        if (s != 0) atomicAdd(&g_diff[plane * BINS + bin], s);
    }

    // Last block finishes the reduction (no separate kernel launch).
    __threadfence();
    if (tid == 0) s_ticket = atomicAdd(&g_count, 1u);
    __syncthreads();
    if (s_ticket == GRID - 1) {
        float s = 0.0f;
        for (int k = tid; k < BC * BINS; k += THREADS) {
            s += fabsf((float)__ldcg(&g_diff[k]));
            g_diff[k] = 0;                     // restore scratch for replay
        }
        #pragma unroll
        for (int o = 16; o > 0; o >>= 1)
            s += __shfl_down_sync(0xFFFFFFFFu, s, o);
        if (lane == 0) ssum[wid] = s;
        __syncthreads();
        if (tid == 0) {
            float t = ssum[0] + ssum[1] + ssum[2] + ssum[3];
            out[0] = t / (262144.0f * (float)(BC * BINS));
            g_count = 0u;                      // restore ticket for replay
        }
    }
}

extern "C" void kernel_launch(void* const* d_in, const int* in_sizes, int n_in,
                              void* d_out, int out_size) {
    const float* inp = (const float*)d_in[0];
    const float* tgt = (const float*)d_in[1];
    float* out = (float*)d_out;

    fused_kernel<<<GRID, THREADS>>>((const float4*)inp, (const float4*)tgt, out);
}

// round 16
// speedup vs baseline: 1.0031x; 1.0031x over previous
#include <cuda_runtime.h>

#define BINS 64
#define BC 96                      // B*C = 32*3
#define PLANE4 65536               // 512*512/4 float4 per (b,c) plane
#define BPP 18                     // chunks per plane
#define THREADS 128
#define WARPS (THREADS / 32)       // 4
#define GRID (BC * BPP)            // 1728 <= 148*12 = 1776 -> SINGLE WAVE

// Signed per-(plane,bin) count diff (+input, -target). Zero at module load;
// the last block restores it to zero each call -> graph-replay safe.
__device__ int g_diff[BC * BINS];
__device__ unsigned int g_count;

// bin = clip(floor((v+1)/step), 0, 63). Input domain [-1,1) => result >= 0.
// Exact-edge disagreement with searchsorted is ~1e-6 relative loss noise.
__device__ __forceinline__ int bin_of(float v) {
    return min(__float2int_rd(fmaf(v, 31.5f, 31.5f)), 63);
}

// s8 packing, 4 bins/word: byte = lane*4 + (bin>>2)*128 + (bin&3)
// -> word = (bin>>2)*32 + lane, so word % 32 == lane for EVERY bin:
// strictly conflict-free LDS/STS, and each lane owns its bytes (no races).
__device__ __forceinline__ int off_of(int b) {
    return ((b & ~3) << 5) | (b & 3);          // (bin>>2)*128 + (bin&3)
}

__global__ __launch_bounds__(THREADS, 12)      // ~40 regs: room for 4-deep MLP
void fused_kernel(const float4* __restrict__ inp, const float4* __restrict__ tgt,
                  float* __restrict__ out) {
    __shared__ signed char hist[WARPS * 2048]; // 8 KB
    __shared__ unsigned int s_ticket;
    __shared__ float ssum[WARPS];

    const int tid  = threadIdx.x;
    const int lane = tid & 31;
    const int wid  = tid >> 5;

    int4* z4 = (int4*)hist;
    #pragma unroll
    for (int i = tid; i < (int)sizeof(hist) / 16; i += THREADS)
        z4[i] = make_int4(0, 0, 0, 0);
    __syncthreads();

    signed char* h = &hist[wid * 2048 + lane * 4];   // lane-owned byte column

    const int plane = blockIdx.x / BPP;
    const int chunk = blockIdx.x % BPP;
    // Exact uneven bounds (PLANE4 not divisible by 18).
    const int start4 = (chunk * PLANE4) / BPP;
    const int end4   = ((chunk + 1) * PLANE4) / BPP;
    const float4* __restrict__ a = inp + (size_t)plane * PLANE4;
    const float4* __restrict__ b = tgt + (size_t)plane * PLANE4;

    // <=114 values/tensor/thread -> per-bin diff in [-114, 114]: s8 ok.
    // 2-way unroll: 4 independent LDG.128 batched ahead of the RMW chain
    // (doubles per-warp MLP — the flat-58%-DRAM plateau across occupancies
    // showed per-warp load depth, not warp count, limits bandwidth).
    int i = start4 + tid;
    for (; i + THREADS < end4; i += 2 * THREADS) {
        float4 v0 = __ldcs(&a[i]);
        float4 v1 = __ldcs(&a[i + THREADS]);
        float4 u0 = __ldcs(&b[i]);
        float4 u1 = __ldcs(&b[i + THREADS]);
        h[off_of(bin_of(v0.x))] += 1;
        h[off_of(bin_of(v0.y))] += 1;
        h[off_of(bin_of(v0.z))] += 1;
        h[off_of(bin_of(v0.w))] += 1;
        h[off_of(bin_of(v1.x))] += 1;
        h[off_of(bin_of(v1.y))] += 1;
        h[off_of(bin_of(v1.z))] += 1;
        h[off_of(bin_of(v1.w))] += 1;
        h[off_of(bin_of(u0.x))] -= 1;
        h[off_of(bin_of(u0.y))] -= 1;
        h[off_of(bin_of(u0.z))] -= 1;
        h[off_of(bin_of(u0.w))] -= 1;
        h[off_of(bin_of(u1.x))] -= 1;
        h[off_of(bin_of(u1.y))] -= 1;
        h[off_of(bin_of(u1.z))] -= 1;
        h[off_of(bin_of(u1.w))] -= 1;
    }
    if (i < end4) {                            // tail: single iteration
        float4 v = __ldcs(&a[i]);
        float4 u = __ldcs(&b[i]);
        h[off_of(bin_of(v.x))] += 1;
        h[off_of(bin_of(v.y))] += 1;
        h[off_of(bin_of(v.z))] += 1;
        h[off_of(bin_of(v.w))] += 1;
        h[off_of(bin_of(u.x))] -= 1;
        h[off_of(bin_of(u.y))] -= 1;
        h[off_of(bin_of(u.z))] -= 1;
        h[off_of(bin_of(u.w))] -= 1;
    }
    __syncthreads();

    // Fold: thread t -> bin = t&63, half = t>>6 (warps 2h, 2h+1). Extract
    // byte (bin&3) from 2 warps x 32 lane-words via masked signed dp4a.
    // Lane rotation (l+t)&31 -> distinct banks within the folding warp.
    {
        const int bin  = tid & 63;
        const int half = tid >> 6;
        const int mask = 1 << ((bin & 3) * 8);
        int s = 0;
        #pragma unroll
        for (int w = 0; w < 2; w++) {
            const int* row = (const int*)hist + (2 * half + w) * 512 + (bin >> 2) * 32;
            #pragma unroll
            for (int l = 0; l < 32; l++)
                s = __dp4a(row[(l + tid) & 31], mask, s);
        }
        if (s != 0) atomicAdd(&g_diff[plane * BINS + bin], s);
    }

    // Last block finishes the reduction (no separate kernel launch).
    __threadfence();
    if (tid == 0) s_ticket = atomicAdd(&g_count, 1u);
    __syncthreads();
    if (s_ticket == GRID - 1) {
        float s = 0.0f;
        for (int k = tid; k < BC * BINS; k += THREADS) {
            s += fabsf((float)__ldcg(&g_diff[k]));
            g_diff[k] = 0;                     // restore scratch for replay
        }
        #pragma unroll
        for (int o = 16; o > 0; o >>= 1)
            s += __shfl_down_sync(0xFFFFFFFFu, s, o);
        if (lane == 0) ssum[wid] = s;
        __syncthreads();
        if (tid == 0) {
            float t = ssum[0] + ssum[1] + ssum[2] + ssum[3];
            out[0] = t / (262144.0f * (float)(BC * BINS));
            g_count = 0u;                      // restore ticket for replay
        }
    }
}

extern "C" void kernel_launch(void* const* d_in, const int* in_sizes, int n_in,
                              void* d_out, int out_size) {
    const float* inp = (const float*)d_in[0];
    const float* tgt = (const float*)d_in[1];
    float* out = (float*)d_out;

    fused_kernel<<<GRID, THREADS>>>((const float4*)inp, (const float4*)tgt, out);
}

// round 17
// speedup vs baseline: 1.0039x; 1.0008x over previous
#include <cuda_runtime.h>

#define BINS 64
#define BC 96                      // B*C = 32*3
#define PLANE4 65536               // 512*512/4 float4 per (b,c) plane
#define BPP 18                     // chunks per plane
#define THREADS 128
#define WARPS (THREADS / 32)       // 4
#define GRID (BC * BPP)            // 1728 <= 148*12 = 1776 -> SINGLE WAVE

// Signed per-(plane,bin) count diff (+input, -target). Zero at module load;
// the last block restores it to zero each call -> graph-replay safe.
__device__ int g_diff[BC * BINS];
__device__ unsigned int g_count;

// bin = clip(floor((v+1)/step), 0, 63). Input domain [-1,1) => result >= 0.
// Exact-edge disagreement with searchsorted is ~1e-6 relative loss noise.
__device__ __forceinline__ int bin_of(float v) {
    return min(__float2int_rd(fmaf(v, 31.5f, 31.5f)), 63);
}

// s8 packing, 4 bins/word: byte = lane*4 + (bin>>2)*128 + (bin&3)
// -> word = (bin>>2)*32 + lane, so word % 32 == lane for EVERY bin:
// strictly conflict-free LDS/STS, and each lane owns its bytes (no races).
__device__ __forceinline__ int off_of(int b) {
    return ((b & ~3) << 5) | (b & 3);          // (bin>>2)*128 + (bin&3)
}

__global__ __launch_bounds__(THREADS, 12)      // ~40 regs: room for 4-deep MLP
void fused_kernel(const float4* __restrict__ inp, const float4* __restrict__ tgt,
                  float* __restrict__ out) {
    __shared__ signed char hist[WARPS * 2048]; // 8 KB
    __shared__ unsigned int s_ticket;
    __shared__ float ssum[WARPS];

    const int tid  = threadIdx.x;
    const int lane = tid & 31;
    const int wid  = tid >> 5;

    int4* z4 = (int4*)hist;
    #pragma unroll
    for (int i = tid; i < (int)sizeof(hist) / 16; i += THREADS)
        z4[i] = make_int4(0, 0, 0, 0);
    __syncthreads();

    signed char* h = &hist[wid * 2048 + lane * 4];   // lane-owned byte column

    const int plane = blockIdx.x / BPP;
    const int chunk = blockIdx.x % BPP;
    // Exact uneven bounds (PLANE4 not divisible by 18).
    const int start4 = (chunk * PLANE4) / BPP;
    const int end4   = ((chunk + 1) * PLANE4) / BPP;
    const float4* __restrict__ a = inp + (size_t)plane * PLANE4;
    const float4* __restrict__ b = tgt + (size_t)plane * PLANE4;

    // <=114 values/tensor/thread -> per-bin diff in [-114, 114]: s8 ok.
    // 2-way unroll: 4 independent LDG.128 batched ahead of the RMW chain
    // (doubles per-warp MLP — the flat-58%-DRAM plateau across occupancies
    // showed per-warp load depth, not warp count, limits bandwidth).
    int i = start4 + tid;
    for (; i + THREADS < end4; i += 2 * THREADS) {
        float4 v0 = __ldcs(&a[i]);
        float4 v1 = __ldcs(&a[i + THREADS]);
        float4 u0 = __ldcs(&b[i]);
        float4 u1 = __ldcs(&b[i + THREADS]);
        h[off_of(bin_of(v0.x))] += 1;
        h[off_of(bin_of(v0.y))] += 1;
        h[off_of(bin_of(v0.z))] += 1;
        h[off_of(bin_of(v0.w))] += 1;
        h[off_of(bin_of(v1.x))] += 1;
        h[off_of(bin_of(v1.y))] += 1;
        h[off_of(bin_of(v1.z))] += 1;
        h[off_of(bin_of(v1.w))] += 1;
        h[off_of(bin_of(u0.x))] -= 1;
        h[off_of(bin_of(u0.y))] -= 1;
        h[off_of(bin_of(u0.z))] -= 1;
        h[off_of(bin_of(u0.w))] -= 1;
        h[off_of(bin_of(u1.x))] -= 1;
        h[off_of(bin_of(u1.y))] -= 1;
        h[off_of(bin_of(u1.z))] -= 1;
        h[off_of(bin_of(u1.w))] -= 1;
    }
    if (i < end4) {                            // tail: single iteration
        float4 v = __ldcs(&a[i]);
        float4 u = __ldcs(&b[i]);
        h[off_of(bin_of(v.x))] += 1;
        h[off_of(bin_of(v.y))] += 1;
        h[off_of(bin_of(v.z))] += 1;
        h[off_of(bin_of(v.w))] += 1;
        h[off_of(bin_of(u.x))] -= 1;
        h[off_of(bin_of(u.y))] -= 1;
        h[off_of(bin_of(u.z))] -= 1;
        h[off_of(bin_of(u.w))] -= 1;
    }
    __syncthreads();

    // Fold: thread t -> bin = t&63, half = t>>6 (warps 2h, 2h+1). Extract
    // byte (bin&3) from 2 warps x 32 lane-words via masked signed dp4a.
    // Lane rotation (l+t)&31 -> distinct banks within the folding warp.
    {
        const int bin  = tid & 63;
        const int half = tid >> 6;
        const int mask = 1 << ((bin & 3) * 8);
        int s = 0;
        #pragma unroll
        for (int w = 0; w < 2; w++) {
            const int* row = (const int*)hist + (2 * half + w) * 512 + (bin >> 2) * 32;
            #pragma unroll
            for (int l = 0; l < 32; l++)
                s = __dp4a(row[(l + tid) & 31], mask, s);
        }
        if (s != 0) atomicAdd(&g_diff[plane * BINS + bin], s);
    }

    // Last block finishes the reduction (no separate kernel launch).
    __threadfence();
    if (tid == 0) s_ticket = atomicAdd(&g_count, 1u);
    __syncthreads();
    if (s_ticket == GRID - 1) {
        float s = 0.0f;
        for (int k = tid; k < BC * BINS; k += THREADS) {
            s += fabsf((float)__ldcg(&g_diff[k]));
            g_diff[k] = 0;                     // restore scratch for replay
        }
        #pragma unroll
        for (int o = 16; o > 0; o >>= 1)
            s += __shfl_down_sync(0xFFFFFFFFu, s, o);
        if (lane == 0) ssum[wid] = s;
        __syncthreads();
        if (tid == 0) {
            float t = ssum[0] + ssum[1] + ssum[2] + ssum[3];
            out[0] = t / (262144.0f * (float)(BC * BINS));
            g_count = 0u;                      // restore ticket for replay
        }
    }
}

extern "C" void kernel_launch(void* const* d_in, const int* in_sizes, int n_in,
                              void* d_out, int out_size) {
    const float* inp = (const float*)d_in[0];
    const float* tgt = (const float*)d_in[1];
    float* out = (float*)d_out;

    fused_kernel<<<GRID, THREADS>>>((const float4*)inp, (const float4*)tgt, out);
}